// round 15
// baseline (speedup 1.0000x reference)
#include <cuda_runtime.h>
#include <cuda_fp16.h>
#include <cstdint>

#define B_      16
#define NP      196
#define NT      197
#define D_      768
#define M_      3072
#define HEADS_  12
#define Y_      64
#define NSTEPS_ 12
#define ALPHA_  0.1f
#define BETA_   0.125f
#define EPS_    1e-5f
#define NMASK_  100
#define RP      3200              // padded row count (25 * 128)
#define QKW     1536              // q|k width
#define ACTW    4608              // [oq|ok|Z] fused activation width
#define FW      4608              // fused fwd output width (q|k|Z)

// ---------------- scratch (device globals; zero-initialized) ----------------
__device__ __half d_patches[RP*D_];
__device__ float  d_tok[B_*NP*D_];
__device__ float  d_x[RP*D_];
__device__ __half d_g[RP*D_];
__device__ __half d_qk[(RP+64)*QKW];
__device__ __half d_act[RP*ACTW];     // cols 0..1535 = [oq|ok], 1536.. = Z
__device__ __half d_Wfwd[FW*D_];      // rows: [WT (hy) | XiT (mu)]; k-major d
__device__ __half d_Wback[D_*ACTW];   // [d][hy | 1536+mu]
__device__ __half d_encTh[D_*D_];
__device__ __half d_decTh[D_*D_];
__device__ float  d_dec[B_*NP*D_];

#define EPI_BIAS    1   // float out + bias, guarded rows
#define EPI_AXPY    3   // float out, C += alpha*acc
#define EPI_QKZ     5   // dual: n0<1536 -> half store to Cv (ld 1536); else relu half to Cv2 (ld 4608)

__device__ __forceinline__ uint32_t smem_u32(const void* p) {
    uint32_t a;
    asm("{ .reg .u64 t; cvta.to.shared.u64 t, %1; cvt.u32.u64 %0, t; }" : "=r"(a) : "l"(p));
    return a;
}
__device__ __forceinline__ void ldsm4(uint32_t* r, uint32_t addr) {
    asm volatile("ldmatrix.sync.aligned.m8n8.x4.shared.b16 {%0,%1,%2,%3}, [%4];"
        : "=r"(r[0]), "=r"(r[1]), "=r"(r[2]), "=r"(r[3]) : "r"(addr));
}
__device__ __forceinline__ void ldsm4t(uint32_t* r, uint32_t addr) {
    asm volatile("ldmatrix.sync.aligned.m8n8.x4.trans.shared.b16 {%0,%1,%2,%3}, [%4];"
        : "=r"(r[0]), "=r"(r[1]), "=r"(r[2]), "=r"(r[3]) : "r"(addr));
}
__device__ __forceinline__ uint32_t packh2(float a, float b) {
    __half2 h = __floats2half2_rn(a, b);
    return *(uint32_t*)&h;
}
#define MMA16(acc, a, b0, b1) \
    asm("mma.sync.aligned.m16n8k16.row.col.f32.f16.f16.f32 " \
        "{%0,%1,%2,%3}, {%4,%5,%6,%7}, {%8,%9}, {%0,%1,%2,%3};" \
        : "+f"((acc)[0]), "+f"((acc)[1]), "+f"((acc)[2]), "+f"((acc)[3]) \
        : "r"((a)[0]), "r"((a)[1]), "r"((a)[2]), "r"((a)[3]), "r"(b0), "r"(b1))

// ---- K-chunk-64 tile loader: R rows x 64 halves, smem stride 72 ----
template<int R>
__device__ __forceinline__ void ldTile64(__half* s, const __half* gp, int ld, int tid) {
#pragma unroll
    for (int i = 0; i < R / 16; i++) {
        int idx = tid + 128 * i;
        int row = idx >> 3, seg = idx & 7;
        asm volatile("cp.async.cg.shared.global [%0], [%1], 16;"
                     :: "r"(smem_u32(s + row * 72 + seg * 8)),
                        "l"(gp + (long long)row * ld + seg * 8));
    }
}

// ================= BT fp16 mma GEMM, K-chunk 64, 2-stage pipeline =================
// C[m,n] (op)= sum_k A[m,k]*B[n,k]; both k-major. Block (WM*32)x128, 4 warps.
template<int EPI, int WM, int MINB, bool GUARD>
__global__ __launch_bounds__(128, MINB) void hbt_kernel(
    const __half* __restrict__ A, const __half* __restrict__ Bm,
    void* __restrict__ Cv, void* __restrict__ Cv2,
    const float* __restrict__ bias,
    int K, int lda, int ldb, int ldc,
    int Mv, int Nv, float alpha)
{
    extern __shared__ __half sh[];
    constexpr int AR  = WM * 32;
    constexpr int STG = (AR + 128) * 72;
    __half* sA[2] = { sh,            sh + STG };
    __half* sB[2] = { sh + AR * 72,  sh + STG + AR * 72 };

    const int tid = threadIdx.x;
    const int lane = tid & 31, wid = tid >> 5;
    const int grp = lane >> 2, tig = lane & 3;
    const int wm = (wid >> 1) * (WM * 16), wn = (wid & 1) * 64;
    const long long m0 = (long long)blockIdx.y * AR;
    const long long n0 = (long long)blockIdx.x * 128;
    A += m0 * lda;
    Bm += n0 * ldb;

    const uint32_t laneoff = (lane & 15) * 144 + (lane >> 4) * 16;

    float acc[WM][8][4];
#pragma unroll
    for (int i = 0; i < WM; i++)
#pragma unroll
        for (int j = 0; j < 8; j++)
#pragma unroll
            for (int c = 0; c < 4; c++) acc[i][j][c] = 0.f;

    const int nk = K >> 6;   // K % 64 == 0 for all call sites
    ldTile64<AR>(sA[0], A, lda, tid);
    ldTile64<128>(sB[0], Bm, ldb, tid);
    asm volatile("cp.async.commit_group;" ::: "memory");

    for (int kt = 0; kt < nk; kt++) {
        if (kt + 1 < nk) {
            int st = (kt + 1) & 1;
            ldTile64<AR>(sA[st], A + (kt + 1) * 64, lda, tid);
            ldTile64<128>(sB[st], Bm + (kt + 1) * 64, ldb, tid);
            asm volatile("cp.async.commit_group;" ::: "memory");
            asm volatile("cp.async.wait_group 1;" ::: "memory");
        } else {
            asm volatile("cp.async.wait_group 0;" ::: "memory");
        }
        __syncthreads();

        const uint32_t aBase = smem_u32(sA[kt & 1]) + wm * 144 + laneoff;
        const uint32_t bBase = smem_u32(sB[kt & 1]) + wn * 144 + laneoff;
#pragma unroll
        for (int kk = 0; kk < 64; kk += 16) {
            uint32_t af[WM][4], bp[4][4];
#pragma unroll
            for (int mt = 0; mt < WM; mt++)
                ldsm4(af[mt], aBase + mt * 16 * 144 + kk * 2);
#pragma unroll
            for (int nb = 0; nb < 4; nb++)
                ldsm4(bp[nb], bBase + nb * 16 * 144 + kk * 2);
#pragma unroll
            for (int mt = 0; mt < WM; mt++)
#pragma unroll
                for (int nt = 0; nt < 8; nt++)
                    MMA16(acc[mt][nt], af[mt],
                          bp[nt >> 1][nt & 1], bp[nt >> 1][2 + (nt & 1)]);
        }
        __syncthreads();
    }

    // ---- epilogues ----
    if (EPI == EPI_QKZ) {
        bool isqk = (n0 < 1536);
        __half* base = isqk ? ((__half*)Cv + n0) : ((__half*)Cv2 + n0);
        int ldx = isqk ? 1536 : ACTW;
#pragma unroll
        for (int mt = 0; mt < WM; mt++) {
            long long r0 = m0 + wm + mt * 16 + grp;
#pragma unroll
            for (int nt = 0; nt < 8; nt++) {
                int col = wn + nt * 8 + 2 * tig;
                float2 v0 = make_float2(acc[mt][nt][0], acc[mt][nt][1]);
                float2 v1 = make_float2(acc[mt][nt][2], acc[mt][nt][3]);
                if (!isqk) {
                    v0.x = fmaxf(v0.x, 0.f); v0.y = fmaxf(v0.y, 0.f);
                    v1.x = fmaxf(v1.x, 0.f); v1.y = fmaxf(v1.y, 0.f);
                }
                *(__half2*)(base + r0 * ldx + col) = __floats2half2_rn(v0.x, v0.y);
                *(__half2*)(base + (r0 + 8) * ldx + col) = __floats2half2_rn(v1.x, v1.y);
            }
        }
    } else if (GUARD) {
        float* Cf = (float*)Cv;
#pragma unroll
        for (int mt = 0; mt < WM; mt++) {
            long long r0 = m0 + wm + mt * 16 + grp;
#pragma unroll
            for (int nt = 0; nt < 8; nt++) {
                long long c = n0 + wn + nt * 8 + 2 * tig;
#pragma unroll
                for (int e = 0; e < 4; e++) {
                    long long r = r0 + (e >> 1) * 8;
                    long long cc = c + (e & 1);
                    if (r < Mv && cc < Nv)
                        Cf[r * ldc + cc] = acc[mt][nt][e] + bias[cc];
                }
            }
        }
    } else {  // EPI_AXPY
        float* Cf = (float*)Cv;
#pragma unroll
        for (int mt = 0; mt < WM; mt++) {
            long long r0 = m0 + wm + mt * 16 + grp;
#pragma unroll
            for (int nt = 0; nt < 8; nt++) {
                int col = nt * 8 + 2 * tig;
                float* c0 = Cf + r0 * ldc + n0 + wn + col;
                float* c1 = c0 + 8LL * ldc;
                float2 o0 = *(float2*)c0;
                float2 o1 = *(float2*)c1;
                o0.x += alpha * acc[mt][nt][0]; o0.y += alpha * acc[mt][nt][1];
                o1.x += alpha * acc[mt][nt][2]; o1.y += alpha * acc[mt][nt][3];
                *(float2*)c0 = o0;
                *(float2*)c1 = o1;
            }
        }
    }
}

// ================= fused attention kernel (R14 register-P form) =================
__global__ __launch_bounds__(256, 1) void attn_kernel(
    const __half* __restrict__ qk, __half* __restrict__ act)
{
    extern __shared__ __half sh[];
    __half* sQ = sh;                   // 256 x 72
    __half* sK = sh + 256 * 72;        // 256 x 72
    __half* sP = sh + 2 * 256 * 72;    // 128 x 232

    const int bh = blockIdx.x;
    const int b = bh / HEADS_, h = bh - b * HEADS_;
    const __half* qbase = qk + (long long)b * NT * QKW + h * 64;
    const __half* kbase = qbase + 768;

    const int tid = threadIdx.x;
    const int lane = tid & 31, w = tid >> 5;
    const int grp = lane >> 2, tig = lane & 3;

    for (int idx = tid; idx < 224 * 8; idx += 256) {
        int row = idx >> 3, seg = idx & 7;
        asm volatile("cp.async.cg.shared.global [%0], [%1], 16;"
                     :: "r"(smem_u32(sQ + row * 72 + seg * 8)),
                        "l"(qbase + (long long)row * QKW + seg * 8));
        asm volatile("cp.async.cg.shared.global [%0], [%1], 16;"
                     :: "r"(smem_u32(sK + row * 72 + seg * 8)),
                        "l"(kbase + (long long)row * QKW + seg * 8));
    }
    for (int idx = tid; idx < 32 * 36; idx += 256) {
        int row = 224 + idx / 36, c = (idx % 36) * 2;
        *(uint32_t*)(sQ + row * 72 + c) = 0;
        *(uint32_t*)(sK + row * 72 + c) = 0;
    }
    asm volatile("cp.async.commit_group;" ::: "memory");
    asm volatile("cp.async.wait_group 0;" ::: "memory");
    __syncthreads();

    const uint32_t sQ32 = smem_u32(sQ), sK32 = smem_u32(sK), sP32 = smem_u32(sP);
    const uint32_t lm16 = (lane & 15);
    const uint32_t lmHi = (lane >> 4) * 16;

    float okacc[2][8][4];
#pragma unroll
    for (int mt = 0; mt < 2; mt++)
#pragma unroll
        for (int nt = 0; nt < 8; nt++)
#pragma unroll
            for (int e = 0; e < 4; e++) okacc[mt][nt][e] = 0.f;

    for (int blk = 0; blk < 2; blk++) {
        const int row0 = blk * 128;

        float sacc[28][4];
#pragma unroll
        for (int nt = 0; nt < 28; nt++)
#pragma unroll
            for (int e = 0; e < 4; e++) sacc[nt][e] = 0.f;

        const uint32_t aBase = sQ32 + (row0 + w * 16 + lm16) * 144 + lmHi;
#pragma unroll
        for (int kc = 0; kc < 4; kc++) {
            uint32_t aq[4];
            ldsm4(aq, aBase + kc * 32);
#pragma unroll
            for (int nb = 0; nb < 14; nb++) {
                uint32_t bp[4];
                ldsm4(bp, sK32 + (nb * 16 + lm16) * 144 + lmHi + kc * 32);
                MMA16(sacc[2 * nb],     aq, bp[0], bp[2]);
                MMA16(sacc[2 * nb + 1], aq, bp[1], bp[3]);
            }
        }

        float m0 = -1e30f, m1 = -1e30f;
#pragma unroll
        for (int nt = 0; nt < 28; nt++) {
            int c0 = nt * 8 + 2 * tig;
            if (c0 >= NT)     { sacc[nt][0] = -1e30f; sacc[nt][2] = -1e30f; }
            if (c0 + 1 >= NT) { sacc[nt][1] = -1e30f; sacc[nt][3] = -1e30f; }
            m0 = fmaxf(m0, fmaxf(sacc[nt][0], sacc[nt][1]));
            m1 = fmaxf(m1, fmaxf(sacc[nt][2], sacc[nt][3]));
        }
        m0 = fmaxf(m0, __shfl_xor_sync(0xffffffffu, m0, 1));
        m0 = fmaxf(m0, __shfl_xor_sync(0xffffffffu, m0, 2));
        m1 = fmaxf(m1, __shfl_xor_sync(0xffffffffu, m1, 1));
        m1 = fmaxf(m1, __shfl_xor_sync(0xffffffffu, m1, 2));
        float s0 = 0.f, s1 = 0.f;
#pragma unroll
        for (int nt = 0; nt < 28; nt++) {
            sacc[nt][0] = __expf(BETA_ * (sacc[nt][0] - m0));
            sacc[nt][1] = __expf(BETA_ * (sacc[nt][1] - m0));
            sacc[nt][2] = __expf(BETA_ * (sacc[nt][2] - m1));
            sacc[nt][3] = __expf(BETA_ * (sacc[nt][3] - m1));
            s0 += sacc[nt][0] + sacc[nt][1];
            s1 += sacc[nt][2] + sacc[nt][3];
        }
        s0 += __shfl_xor_sync(0xffffffffu, s0, 1);
        s0 += __shfl_xor_sync(0xffffffffu, s0, 2);
        s1 += __shfl_xor_sync(0xffffffffu, s1, 1);
        s1 += __shfl_xor_sync(0xffffffffu, s1, 2);
        float i0 = 1.f / s0, i1 = 1.f / s1;

#pragma unroll
        for (int nt = 0; nt < 28; nt++) {
            sacc[nt][0] *= i0; sacc[nt][1] *= i0;
            sacc[nt][2] *= i1; sacc[nt][3] *= i1;
        }

        const int rl = w * 16 + grp;
        const bool rv0 = (row0 + rl) < NT;
        const bool rv1 = (row0 + rl + 8) < NT;
#pragma unroll
        for (int nt = 0; nt < 28; nt++) {
            __half2 h0 = rv0 ? __floats2half2_rn(sacc[nt][0], sacc[nt][1])
                             : __floats2half2_rn(0.f, 0.f);
            __half2 h1 = rv1 ? __floats2half2_rn(sacc[nt][2], sacc[nt][3])
                             : __floats2half2_rn(0.f, 0.f);
            *(__half2*)(sP + rl * 232 + nt * 8 + 2 * tig) = h0;
            *(__half2*)(sP + (rl + 8) * 232 + nt * 8 + 2 * tig) = h1;
        }

        // oq = P @ k : P straight from registers
        float oqa[8][4];
#pragma unroll
        for (int nt = 0; nt < 8; nt++)
#pragma unroll
            for (int e = 0; e < 4; e++) oqa[nt][e] = 0.f;

#pragma unroll
        for (int mc = 0; mc < 14; mc++) {
            uint32_t ap[4];
            ap[0] = packh2(sacc[2 * mc][0],     sacc[2 * mc][1]);
            ap[1] = packh2(sacc[2 * mc][2],     sacc[2 * mc][3]);
            ap[2] = packh2(sacc[2 * mc + 1][0], sacc[2 * mc + 1][1]);
            ap[3] = packh2(sacc[2 * mc + 1][2], sacc[2 * mc + 1][3]);
            uint32_t bq[4][4];
#pragma unroll
            for (int yb = 0; yb < 4; yb++)
                ldsm4t(bq[yb], sK32 + (mc * 16 + lm16) * 144 + lmHi + yb * 32);
#pragma unroll
            for (int nt = 0; nt < 8; nt++)
                MMA16(oqa[nt], ap, bq[nt >> 1][(nt & 1) * 2], bq[nt >> 1][(nt & 1) * 2 + 1]);
        }
        {
            int gr = row0 + w * 16 + grp;
            if (gr < NT) {
                __half* dst = act + ((long long)(b * NT + gr)) * ACTW + h * 64;
#pragma unroll
                for (int nt = 0; nt < 8; nt++)
                    *(__half2*)(dst + nt * 8 + 2 * tig) = __floats2half2_rn(oqa[nt][0], oqa[nt][1]);
            }
            if (gr + 8 < NT) {
                __half* dst = act + ((long long)(b * NT + gr + 8)) * ACTW + h * 64;
#pragma unroll
                for (int nt = 0; nt < 8; nt++)
                    *(__half2*)(dst + nt * 8 + 2 * tig) = __floats2half2_rn(oqa[nt][2], oqa[nt][3]);
            }
        }
        __syncthreads();

        // ok += P^T @ q
#pragma unroll
        for (int rc = 0; rc < 8; rc++) {
            uint32_t bq[4][4];
#pragma unroll
            for (int yb = 0; yb < 4; yb++)
                ldsm4t(bq[yb], sQ32 + (row0 + rc * 16 + lm16) * 144 + lmHi + yb * 32);
#pragma unroll
            for (int mt = 0; mt < 2; mt++) {
                if (mt == 0 || w < 6) {
                    int t = w + mt * 8;
                    uint32_t tmp[4];
                    ldsm4t(tmp, sP32 + (rc * 16 + lm16) * 464 + lmHi + t * 32);
                    uint32_t ap[4] = { tmp[0], tmp[2], tmp[1], tmp[3] };
#pragma unroll
                    for (int nt = 0; nt < 8; nt++)
                        MMA16(okacc[mt][nt], ap,
                              bq[nt >> 1][(nt & 1) * 2], bq[nt >> 1][(nt & 1) * 2 + 1]);
                }
            }
        }
        __syncthreads();
    }

#pragma unroll
    for (int mt = 0; mt < 2; mt++) {
        if (mt == 0 || w < 6) {
            int t = w + mt * 8;
            int c0 = t * 16 + grp;
            if (c0 < NT) {
                __half* dst = act + ((long long)(b * NT + c0)) * ACTW + 768 + h * 64;
#pragma unroll
                for (int nt = 0; nt < 8; nt++)
                    *(__half2*)(dst + nt * 8 + 2 * tig) = __floats2half2_rn(okacc[mt][nt][0], okacc[mt][nt][1]);
            }
            if (c0 + 8 < NT) {
                __half* dst = act + ((long long)(b * NT + c0 + 8)) * ACTW + 768 + h * 64;
#pragma unroll
                for (int nt = 0; nt < 8; nt++)
                    *(__half2*)(dst + nt * 8 + 2 * tig) = __floats2half2_rn(okacc[mt][nt][2], okacc[mt][nt][3]);
            }
        }
    }
}

// ================= layernorm (fp32 in, half out) =================
__device__ __forceinline__ float block_sum256(float v, float* red) {
    int lane = threadIdx.x & 31, w = threadIdx.x >> 5;
#pragma unroll
    for (int o = 16; o > 0; o >>= 1) v += __shfl_xor_sync(0xffffffffu, v, o);
    if (lane == 0) red[w] = v;
    __syncthreads();
    float s = 0.f;
#pragma unroll
    for (int i = 0; i < 8; i++) s += red[i];
    __syncthreads();
    return s;
}

__global__ void lnorm_kernel(const float* __restrict__ x, __half* __restrict__ g,
                             const float* __restrict__ gamma_p,
                             const float* __restrict__ delta, int skipcls)
{
    __shared__ float red[8];
    int r = blockIdx.x;
    const float* xr;
    __half* gr;
    if (skipcls) {
        int b = r / NP, i = r - b * NP;
        xr = x + (long long)(b * NT + 1 + i) * D_;
        gr = g + (long long)r * D_;
    } else {
        xr = x + (long long)r * D_;
        gr = g + (long long)r * D_;
    }
    int t = threadIdx.x; // 256
    float v0 = xr[t], v1 = xr[t + 256], v2 = xr[t + 512];
    float mean = block_sum256(v0 + v1 + v2, red) * (1.f / 768.f);
    float c0 = v0 - mean, c1 = v1 - mean, c2 = v2 - mean;
    float var = block_sum256(c0*c0 + c1*c1 + c2*c2, red) * (1.f / 768.f);
    float rinv = rsqrtf(var + EPS_);
    float gm = gamma_p[0];
    gr[t]       = __float2half(gm * c0 * rinv + delta[t]);
    gr[t + 256] = __float2half(gm * c1 * rinv + delta[t + 256]);
    gr[t + 512] = __float2half(gm * c2 * rinv + delta[t + 512]);
}

// ================= weight prep =================
__global__ void build_wqk_kernel(const float* __restrict__ Wq, const float* __restrict__ Wk,
                                 __half* __restrict__ Wfwd, __half* __restrict__ Wback)
{
    int idx = blockIdx.x * 256 + threadIdx.x;
    if (idx >= 2 * D_ * D_) return;
    int which = idx >= D_ * D_;
    int r = idx - which * D_ * D_;
    int h = r / (D_ * Y_);
    int rem = r - h * (D_ * Y_);
    int d = rem / Y_;
    int y = rem - d * Y_;
    __half v = __float2half(which ? Wk[r] : Wq[r]);
    int hy = h * Y_ + y + which * D_;
    Wfwd[(long long)hy * D_ + d] = v;
    Wback[(long long)d * ACTW + hy] = v;
}

__global__ void build_xi_kernel(const float* __restrict__ Xi,
                                __half* __restrict__ Wfwd, __half* __restrict__ Wback)
{
    __shared__ __half t[32][33];
    int d0 = blockIdx.y * 32, m0 = blockIdx.x * 32;
    int tx = threadIdx.x & 31, ty = threadIdx.x >> 5;
#pragma unroll
    for (int i = 0; i < 32; i += 8) {
        __half v = __float2half(Xi[(long long)(d0 + ty + i) * M_ + m0 + tx]);
        Wback[(long long)(d0 + ty + i) * ACTW + 1536 + m0 + tx] = v;
        t[ty + i][tx] = v;
    }
    __syncthreads();
#pragma unroll
    for (int i = 0; i < 32; i += 8)
        Wfwd[(long long)(1536 + m0 + ty + i) * D_ + d0 + tx] = t[tx][ty + i];
}

__global__ void build_wt_kernel(const float* __restrict__ W, __half* __restrict__ WT)
{
    __shared__ __half t[32][33];
    int i0 = blockIdx.y * 32, j0 = blockIdx.x * 32;
    int tx = threadIdx.x & 31, ty = threadIdx.x >> 5;
#pragma unroll
    for (int i = 0; i < 32; i += 8)
        t[ty + i][tx] = __float2half(W[(long long)(i0 + ty + i) * D_ + j0 + tx]);
    __syncthreads();
#pragma unroll
    for (int i = 0; i < 32; i += 8)
        WT[(long long)(j0 + ty + i) * D_ + i0 + tx] = t[tx][ty + i];
}

// ================= misc =================
__global__ void patchify_kernel(const float* __restrict__ img, __half* __restrict__ out)
{
    int idx = blockIdx.x * 256 + threadIdx.x;
    if (idx >= B_ * NP * D_) return;
    int e = idx % D_;
    int rest = idx / D_;
    int p = rest % NP;
    int b = rest / NP;
    int c = e >> 8;
    int r = (e >> 4) & 15;
    int col = e & 15;
    int kh = p / 14, kw = p - kh * 14;
    out[idx] = __float2half(img[((long long)(b * 3 + c) * 224 + kh * 16 + r) * 224 + kw * 16 + col]);
}

__global__ void unpatchify_kernel(const float* __restrict__ dec, float* __restrict__ out)
{
    int idx = blockIdx.x * 256 + threadIdx.x;
    if (idx >= B_ * 3 * 224 * 224) return;
    int w = idx % 224;
    int rest = idx / 224;
    int h = rest % 224;
    rest /= 224;
    int c = rest % 3;
    int b = rest / 3;
    int kh = h >> 4, r = h & 15, kw = w >> 4, col = w & 15;
    out[idx] = dec[(long long)(b * NP + kh * 14 + kw) * D_ + c * 256 + r * 16 + col];
}

__global__ void build_x_kernel(const float* __restrict__ tok, const int* __restrict__ mask,
                               const float* __restrict__ cls, const float* __restrict__ mtok,
                               const float* __restrict__ pos, float* __restrict__ x)
{
    __shared__ int sm[NP];
    __shared__ unsigned char flag[NP];
    __shared__ int count_s;
    int b = blockIdx.x;
    int t = threadIdx.x; // 256
    if (t < NP) sm[t] = mask[b * NP + t];
    __syncthreads();
    if (t < NP) {
        int pref = 0;
        for (int j = 0; j < t; j++) pref += (sm[j] == 1);
        flag[t] = (sm[t] == 1 && pref < NMASK_) ? 1 : 0;
        if (t == NP - 1) count_s = pref + (sm[t] == 1);
    }
    __syncthreads();
    if (t == 0 && count_s < NMASK_) flag[0] = 1; // fill_value=0 padding hits token 0
    __syncthreads();
    for (int tk = 0; tk < NT; tk++) {
        const float* src;
        if (tk == 0) src = cls;
        else if (flag[tk - 1]) src = mtok;
        else src = tok + (long long)(b * NP + tk - 1) * D_;
        float* dst = x + (long long)(b * NT + tk) * D_;
        const float* pr = pos + (long long)tk * D_;
        for (int d = t; d < D_; d += 256) dst[d] = src[d] + pr[d];
    }
}

// ================= host wrappers =================
template<int EPI, int WM, int MINB, bool GUARD>
static void launch_bt(const __half* A, const __half* B, void* C, void* C2,
                      const float* bias, int Mtiles, int Ntiles, int K,
                      int lda, int ldb, int ldc, int Mv, int Nv, float alpha)
{
    int smem = 2 * (WM * 32 + 128) * 72 * 2;
    cudaFuncSetAttribute(hbt_kernel<EPI, WM, MINB, GUARD>,
                         cudaFuncAttributeMaxDynamicSharedMemorySize, smem);
    dim3 g(Ntiles, Mtiles, 1);
    hbt_kernel<EPI, WM, MINB, GUARD><<<g, 128, smem>>>(A, B, C, C2, bias, K,
                                                       lda, ldb, ldc, Mv, Nv, alpha);
}

extern "C" void kernel_launch(void* const* d_in, const int* in_sizes, int n_in,
                              void* d_out, int out_size)
{
    const float* img   = (const float*)d_in[0];
    const int*   mask  = (const int*)  d_in[1];
    const float* enc_W = (const float*)d_in[2];
    const float* enc_b = (const float*)d_in[3];
    const float* dec_W = (const float*)d_in[4];
    const float* dec_b = (const float*)d_in[5];
    const float* cls   = (const float*)d_in[6];
    const float* mtok  = (const float*)d_in[7];
    const float* pos   = (const float*)d_in[8];
    const float* Wq    = (const float*)d_in[9];
    const float* Wk    = (const float*)d_in[10];
    const float* Xi    = (const float*)d_in[11];
    const float* gamma = (const float*)d_in[12];
    const float* delta = (const float*)d_in[13];
    float* out = (float*)d_out;

    __half *ppatH, *pgH, *pqkH, *pact, *pWfwd, *pWback, *pencTh, *pdecTh;
    float *ptok, *px, *pdec;
    cudaGetSymbolAddress((void**)&ppatH, d_patches);
    cudaGetSymbolAddress((void**)&ptok,  d_tok);
    cudaGetSymbolAddress((void**)&px,    d_x);
    cudaGetSymbolAddress((void**)&pgH,   d_g);
    cudaGetSymbolAddress((void**)&pqkH,  d_qk);
    cudaGetSymbolAddress((void**)&pact,  d_act);
    cudaGetSymbolAddress((void**)&pWfwd, d_Wfwd);
    cudaGetSymbolAddress((void**)&pWback, d_Wback);
    cudaGetSymbolAddress((void**)&pencTh, d_encTh);
    cudaGetSymbolAddress((void**)&pdecTh, d_decTh);
    cudaGetSymbolAddress((void**)&pdec,  d_dec);

    const int ROWS  = B_ * NT;   // 3152
    const int ROWSE = B_ * NP;   // 3136

    // weight prep
    build_wqk_kernel<<<(2 * D_ * D_ + 255) / 256, 256>>>(Wq, Wk, pWfwd, pWback);
    build_xi_kernel<<<dim3(M_ / 32, D_ / 32), 256>>>(Xi, pWfwd, pWback);
    build_wt_kernel<<<dim3(24, 24), 256>>>(enc_W, pencTh);
    build_wt_kernel<<<dim3(24, 24), 256>>>(dec_W, pdecTh);

    // encode
    patchify_kernel<<<(B_ * NP * D_ + 255) / 256, 256>>>(img, ppatH);
    launch_bt<EPI_BIAS, 4, 2, true>(ppatH, pencTh, ptok, 0, enc_b,
        25, 6, D_, D_, D_, D_, ROWSE, D_, 0.f);
    build_x_kernel<<<B_, 256>>>(ptok, mask, cls, mtok, pos, px);

    int attn_smem = (2 * 256 * 72 + 128 * 232) * 2;   // 133120
    cudaFuncSetAttribute(attn_kernel,
                         cudaFuncAttributeMaxDynamicSharedMemorySize, attn_smem);

    for (int s = 0; s < NSTEPS_; s++) {
        lnorm_kernel<<<ROWS, 256>>>(px, pgH, gamma, delta, 0);
        // fused fwd: [q|k | Z] = g @ [WT ; XiT]
        launch_bt<EPI_QKZ, 4, 2, false>(pgH, pWfwd, pqkH, pact, 0,
            25, 36, D_, D_, D_, 0, 0, 0, 0.f);
        // fused attention: act[.,0..1535] <- [P@k | P^T@q]
        attn_kernel<<<B_ * HEADS_, 256, attn_smem>>>(pqkH, pact);
        // fused bwd: x += alpha * [oq|ok|Z] @ [W2 ; XiR]
        launch_bt<EPI_AXPY, 2, 3, false>(pact, pWback, px, 0, 0,
            50, 6, ACTW, ACTW, ACTW, D_, 0, 0, ALPHA_);
    }

    // decode
    lnorm_kernel<<<ROWSE, 256>>>(px, pgH, gamma, delta, 1);
    launch_bt<EPI_BIAS, 4, 2, true>(pgH, pdecTh, pdec, 0, dec_b,
        25, 6, D_, D_, D_, D_, ROWSE, D_, 0.f);
    unpatchify_kernel<<<(B_ * 3 * 224 * 224 + 255) / 256, 256>>>(pdec, out);
}

// round 16
// speedup vs baseline: 1.3499x; 1.3499x over previous
#include <cuda_runtime.h>
#include <cuda_fp16.h>
#include <cstdint>

#define B_      16
#define NP      196
#define NT      197
#define D_      768
#define M_      3072
#define HEADS_  12
#define Y_      64
#define NSTEPS_ 12
#define ALPHA_  0.1f
#define BETA_   0.125f
#define EPS_    1e-5f
#define NMASK_  100
#define RP      3200              // padded row count (25 * 128)
#define QKW     1536              // q|k width
#define ACTW    4608              // [oq|ok|Z] fused activation width
#define FW      4608              // fused fwd output width (q|k|Z)

// ---------------- scratch (device globals; zero-initialized) ----------------
__device__ __half d_patches[RP*D_];
__device__ float  d_tok[B_*NP*D_];
__device__ float  d_x[RP*D_];
__device__ __half d_g[RP*D_];
__device__ __half d_qk[(RP+64)*QKW];
__device__ __half d_act[RP*ACTW];     // cols 0..1535 = [oq|ok], 1536.. = Z
__device__ __half d_Wfwd[FW*D_];      // rows: [WT (hy) | XiT (mu)]; k-major d
__device__ __half d_Wback[D_*ACTW];   // [d][hy | 1536+mu]
__device__ __half d_encTh[D_*D_];
__device__ __half d_decTh[D_*D_];
__device__ float  d_dec[B_*NP*D_];

#define EPI_BIAS    1   // float out + bias, guarded rows
#define EPI_AXPY    3   // float out, C += alpha*acc
#define EPI_QKZ     5   // dual: n0<1536 -> half store to Cv (ld 1536); else relu half to Cv2 (ld 4608)

__device__ __forceinline__ uint32_t smem_u32(const void* p) {
    uint32_t a;
    asm("{ .reg .u64 t; cvta.to.shared.u64 t, %1; cvt.u32.u64 %0, t; }" : "=r"(a) : "l"(p));
    return a;
}
__device__ __forceinline__ void ldsm4(uint32_t* r, uint32_t addr) {
    asm volatile("ldmatrix.sync.aligned.m8n8.x4.shared.b16 {%0,%1,%2,%3}, [%4];"
        : "=r"(r[0]), "=r"(r[1]), "=r"(r[2]), "=r"(r[3]) : "r"(addr));
}
__device__ __forceinline__ void ldsm4t(uint32_t* r, uint32_t addr) {
    asm volatile("ldmatrix.sync.aligned.m8n8.x4.trans.shared.b16 {%0,%1,%2,%3}, [%4];"
        : "=r"(r[0]), "=r"(r[1]), "=r"(r[2]), "=r"(r[3]) : "r"(addr));
}
__device__ __forceinline__ uint32_t packh2(float a, float b) {
    __half2 h = __floats2half2_rn(a, b);
    return *(uint32_t*)&h;
}
#define MMA16(acc, a, b0, b1) \
    asm("mma.sync.aligned.m16n8k16.row.col.f32.f16.f16.f32 " \
        "{%0,%1,%2,%3}, {%4,%5,%6,%7}, {%8,%9}, {%0,%1,%2,%3};" \
        : "+f"((acc)[0]), "+f"((acc)[1]), "+f"((acc)[2]), "+f"((acc)[3]) \
        : "r"((a)[0]), "r"((a)[1]), "r"((a)[2]), "r"((a)[3]), "r"(b0), "r"(b1))

// ---- generic tile loader: R rows x 32 halves, smem stride 40 ----
template<int R>
__device__ __forceinline__ void ldTile(__half* s, const __half* gp, int ld, int tid) {
#pragma unroll
    for (int i = 0; i < R / 32; i++) {
        int idx = tid + 128 * i;
        int row = idx >> 2, seg = idx & 3;
        asm volatile("cp.async.cg.shared.global [%0], [%1], 16;"
                     :: "r"(smem_u32(s + row * 40 + seg * 8)),
                        "l"(gp + (long long)row * ld + seg * 8));
    }
}

// ================= BT fp16 mma GEMM, 4-stage pipeline, K-chunk 32 =================
// C[m,n] (op)= sum_k A[m,k]*B[n,k]; both k-major. Block (WM*32)x128, 4 warps.
template<int EPI, int WM, int MINB, bool GUARD>
__global__ __launch_bounds__(128, MINB) void hbt_kernel(
    const __half* __restrict__ A, const __half* __restrict__ Bm,
    void* __restrict__ Cv, void* __restrict__ Cv2,
    const float* __restrict__ bias,
    int K, int lda, int ldb, int ldc,
    int Mv, int Nv, float alpha)
{
    extern __shared__ __half sh[];
    constexpr int AR  = WM * 32;
    constexpr int STG = (AR + 128) * 40;
    __half* sA[4] = { sh, sh + STG, sh + 2 * STG, sh + 3 * STG };
    __half* sB[4] = { sh + AR * 40, sh + STG + AR * 40,
                      sh + 2 * STG + AR * 40, sh + 3 * STG + AR * 40 };

    const int tid = threadIdx.x;
    const int lane = tid & 31, wid = tid >> 5;
    const int grp = lane >> 2, tig = lane & 3;
    const int wm = (wid >> 1) * (WM * 16), wn = (wid & 1) * 64;
    const long long m0 = (long long)blockIdx.y * AR;
    const long long n0 = (long long)blockIdx.x * 128;
    A += m0 * lda;
    Bm += n0 * ldb;

    const uint32_t laneoff = (lane & 15) * 80 + (lane >> 4) * 16;

    float acc[WM][8][4];
#pragma unroll
    for (int i = 0; i < WM; i++)
#pragma unroll
        for (int j = 0; j < 8; j++)
#pragma unroll
            for (int c = 0; c < 4; c++) acc[i][j][c] = 0.f;

    const int nk = K >> 5;   // always >= 24 here
#pragma unroll
    for (int p = 0; p < 3; p++) {
        ldTile<AR>(sA[p], A + p * 32, lda, tid);
        ldTile<128>(sB[p], Bm + p * 32, ldb, tid);
        asm volatile("cp.async.commit_group;" ::: "memory");
    }

    for (int kt = 0; kt < nk; kt++) {
        if (kt + 1 < nk)
            asm volatile("cp.async.wait_group 2;" ::: "memory");
        else
            asm volatile("cp.async.wait_group 0;" ::: "memory");
        __syncthreads();

        if (kt + 3 < nk) {
            int ls = (kt + 3) & 3;
            ldTile<AR>(sA[ls], A + (kt + 3) * 32, lda, tid);
            ldTile<128>(sB[ls], Bm + (kt + 3) * 32, ldb, tid);
            asm volatile("cp.async.commit_group;" ::: "memory");
        }

        const uint32_t aBase = smem_u32(sA[kt & 3]) + wm * 80 + laneoff;
        const uint32_t bBase = smem_u32(sB[kt & 3]) + wn * 80 + laneoff;
#pragma unroll
        for (int kk = 0; kk < 32; kk += 16) {
            uint32_t af[WM][4], bp[4][4];
#pragma unroll
            for (int mt = 0; mt < WM; mt++)
                ldsm4(af[mt], aBase + mt * 16 * 80 + kk * 2);
#pragma unroll
            for (int nb = 0; nb < 4; nb++)
                ldsm4(bp[nb], bBase + nb * 16 * 80 + kk * 2);
#pragma unroll
            for (int mt = 0; mt < WM; mt++)
#pragma unroll
                for (int nt = 0; nt < 8; nt++)
                    MMA16(acc[mt][nt], af[mt],
                          bp[nt >> 1][nt & 1], bp[nt >> 1][2 + (nt & 1)]);
        }
        __syncthreads();
    }

    // ---- epilogues ----
    if (EPI == EPI_QKZ) {
        bool isqk = (n0 < 1536);
        __half* base = isqk ? ((__half*)Cv + n0) : ((__half*)Cv2 + n0);
        int ldx = isqk ? 1536 : ACTW;
#pragma unroll
        for (int mt = 0; mt < WM; mt++) {
            long long r0 = m0 + wm + mt * 16 + grp;
#pragma unroll
            for (int nt = 0; nt < 8; nt++) {
                int col = wn + nt * 8 + 2 * tig;
                float2 v0 = make_float2(acc[mt][nt][0], acc[mt][nt][1]);
                float2 v1 = make_float2(acc[mt][nt][2], acc[mt][nt][3]);
                if (!isqk) {
                    v0.x = fmaxf(v0.x, 0.f); v0.y = fmaxf(v0.y, 0.f);
                    v1.x = fmaxf(v1.x, 0.f); v1.y = fmaxf(v1.y, 0.f);
                }
                *(__half2*)(base + r0 * ldx + col) = __floats2half2_rn(v0.x, v0.y);
                *(__half2*)(base + (r0 + 8) * ldx + col) = __floats2half2_rn(v1.x, v1.y);
            }
        }
    } else if (GUARD) {
        float* Cf = (float*)Cv;
#pragma unroll
        for (int mt = 0; mt < WM; mt++) {
            long long r0 = m0 + wm + mt * 16 + grp;
#pragma unroll
            for (int nt = 0; nt < 8; nt++) {
                long long c = n0 + wn + nt * 8 + 2 * tig;
#pragma unroll
                for (int e = 0; e < 4; e++) {
                    long long r = r0 + (e >> 1) * 8;
                    long long cc = c + (e & 1);
                    if (r < Mv && cc < Nv)
                        Cf[r * ldc + cc] = acc[mt][nt][e] + bias[cc];
                }
            }
        }
    } else {  // EPI_AXPY
        float* Cf = (float*)Cv;
#pragma unroll
        for (int mt = 0; mt < WM; mt++) {
            long long r0 = m0 + wm + mt * 16 + grp;
#pragma unroll
            for (int nt = 0; nt < 8; nt++) {
                int col = nt * 8 + 2 * tig;
                float* c0 = Cf + r0 * ldc + n0 + wn + col;
                float* c1 = c0 + 8LL * ldc;
                float2 o0 = *(float2*)c0;
                float2 o1 = *(float2*)c1;
                o0.x += alpha * acc[mt][nt][0]; o0.y += alpha * acc[mt][nt][1];
                o1.x += alpha * acc[mt][nt][2]; o1.y += alpha * acc[mt][nt][3];
                *(float2*)c0 = o0;
                *(float2*)c1 = o1;
            }
        }
    }
}

// ================= fused attention kernel (R14 register-P form) =================
__global__ __launch_bounds__(256, 1) void attn_kernel(
    const __half* __restrict__ qk, __half* __restrict__ act)
{
    extern __shared__ __half sh[];
    __half* sQ = sh;                   // 256 x 72
    __half* sK = sh + 256 * 72;        // 256 x 72
    __half* sP = sh + 2 * 256 * 72;    // 128 x 232

    const int bh = blockIdx.x;
    const int b = bh / HEADS_, h = bh - b * HEADS_;
    const __half* qbase = qk + (long long)b * NT * QKW + h * 64;
    const __half* kbase = qbase + 768;

    const int tid = threadIdx.x;
    const int lane = tid & 31, w = tid >> 5;
    const int grp = lane >> 2, tig = lane & 3;

    for (int idx = tid; idx < 224 * 8; idx += 256) {
        int row = idx >> 3, seg = idx & 7;
        asm volatile("cp.async.cg.shared.global [%0], [%1], 16;"
                     :: "r"(smem_u32(sQ + row * 72 + seg * 8)),
                        "l"(qbase + (long long)row * QKW + seg * 8));
        asm volatile("cp.async.cg.shared.global [%0], [%1], 16;"
                     :: "r"(smem_u32(sK + row * 72 + seg * 8)),
                        "l"(kbase + (long long)row * QKW + seg * 8));
    }
    for (int idx = tid; idx < 32 * 36; idx += 256) {
        int row = 224 + idx / 36, c = (idx % 36) * 2;
        *(uint32_t*)(sQ + row * 72 + c) = 0;
        *(uint32_t*)(sK + row * 72 + c) = 0;
    }
    asm volatile("cp.async.commit_group;" ::: "memory");
    asm volatile("cp.async.wait_group 0;" ::: "memory");
    __syncthreads();

    const uint32_t sQ32 = smem_u32(sQ), sK32 = smem_u32(sK), sP32 = smem_u32(sP);
    const uint32_t lm16 = (lane & 15);
    const uint32_t lmHi = (lane >> 4) * 16;

    float okacc[2][8][4];
#pragma unroll
    for (int mt = 0; mt < 2; mt++)
#pragma unroll
        for (int nt = 0; nt < 8; nt++)
#pragma unroll
            for (int e = 0; e < 4; e++) okacc[mt][nt][e] = 0.f;

    for (int blk = 0; blk < 2; blk++) {
        const int row0 = blk * 128;

        float sacc[28][4];
#pragma unroll
        for (int nt = 0; nt < 28; nt++)
#pragma unroll
            for (int e = 0; e < 4; e++) sacc[nt][e] = 0.f;

        const uint32_t aBase = sQ32 + (row0 + w * 16 + lm16) * 144 + lmHi;
#pragma unroll
        for (int kc = 0; kc < 4; kc++) {
            uint32_t aq[4];
            ldsm4(aq, aBase + kc * 32);
#pragma unroll
            for (int nb = 0; nb < 14; nb++) {
                uint32_t bp[4];
                ldsm4(bp, sK32 + (nb * 16 + lm16) * 144 + lmHi + kc * 32);
                MMA16(sacc[2 * nb],     aq, bp[0], bp[2]);
                MMA16(sacc[2 * nb + 1], aq, bp[1], bp[3]);
            }
        }

        float m0 = -1e30f, m1 = -1e30f;
#pragma unroll
        for (int nt = 0; nt < 28; nt++) {
            int c0 = nt * 8 + 2 * tig;
            if (c0 >= NT)     { sacc[nt][0] = -1e30f; sacc[nt][2] = -1e30f; }
            if (c0 + 1 >= NT) { sacc[nt][1] = -1e30f; sacc[nt][3] = -1e30f; }
            m0 = fmaxf(m0, fmaxf(sacc[nt][0], sacc[nt][1]));
            m1 = fmaxf(m1, fmaxf(sacc[nt][2], sacc[nt][3]));
        }
        m0 = fmaxf(m0, __shfl_xor_sync(0xffffffffu, m0, 1));
        m0 = fmaxf(m0, __shfl_xor_sync(0xffffffffu, m0, 2));
        m1 = fmaxf(m1, __shfl_xor_sync(0xffffffffu, m1, 1));
        m1 = fmaxf(m1, __shfl_xor_sync(0xffffffffu, m1, 2));
        float s0 = 0.f, s1 = 0.f;
#pragma unroll
        for (int nt = 0; nt < 28; nt++) {
            sacc[nt][0] = __expf(BETA_ * (sacc[nt][0] - m0));
            sacc[nt][1] = __expf(BETA_ * (sacc[nt][1] - m0));
            sacc[nt][2] = __expf(BETA_ * (sacc[nt][2] - m1));
            sacc[nt][3] = __expf(BETA_ * (sacc[nt][3] - m1));
            s0 += sacc[nt][0] + sacc[nt][1];
            s1 += sacc[nt][2] + sacc[nt][3];
        }
        s0 += __shfl_xor_sync(0xffffffffu, s0, 1);
        s0 += __shfl_xor_sync(0xffffffffu, s0, 2);
        s1 += __shfl_xor_sync(0xffffffffu, s1, 1);
        s1 += __shfl_xor_sync(0xffffffffu, s1, 2);
        float i0 = 1.f / s0, i1 = 1.f / s1;

#pragma unroll
        for (int nt = 0; nt < 28; nt++) {
            sacc[nt][0] *= i0; sacc[nt][1] *= i0;
            sacc[nt][2] *= i1; sacc[nt][3] *= i1;
        }

        const int rl = w * 16 + grp;
        const bool rv0 = (row0 + rl) < NT;
        const bool rv1 = (row0 + rl + 8) < NT;
#pragma unroll
        for (int nt = 0; nt < 28; nt++) {
            __half2 h0 = rv0 ? __floats2half2_rn(sacc[nt][0], sacc[nt][1])
                             : __floats2half2_rn(0.f, 0.f);
            __half2 h1 = rv1 ? __floats2half2_rn(sacc[nt][2], sacc[nt][3])
                             : __floats2half2_rn(0.f, 0.f);
            *(__half2*)(sP + rl * 232 + nt * 8 + 2 * tig) = h0;
            *(__half2*)(sP + (rl + 8) * 232 + nt * 8 + 2 * tig) = h1;
        }

        // oq = P @ k : P straight from registers
        float oqa[8][4];
#pragma unroll
        for (int nt = 0; nt < 8; nt++)
#pragma unroll
            for (int e = 0; e < 4; e++) oqa[nt][e] = 0.f;

#pragma unroll
        for (int mc = 0; mc < 14; mc++) {
            uint32_t ap[4];
            ap[0] = packh2(sacc[2 * mc][0],     sacc[2 * mc][1]);
            ap[1] = packh2(sacc[2 * mc][2],     sacc[2 * mc][3]);
            ap[2] = packh2(sacc[2 * mc + 1][0], sacc[2 * mc + 1][1]);
            ap[3] = packh2(sacc[2 * mc + 1][2], sacc[2 * mc + 1][3]);
            uint32_t bq[4][4];
#pragma unroll
            for (int yb = 0; yb < 4; yb++)
                ldsm4t(bq[yb], sK32 + (mc * 16 + lm16) * 144 + lmHi + yb * 32);
#pragma unroll
            for (int nt = 0; nt < 8; nt++)
                MMA16(oqa[nt], ap, bq[nt >> 1][(nt & 1) * 2], bq[nt >> 1][(nt & 1) * 2 + 1]);
        }
        {
            int gr = row0 + w * 16 + grp;
            if (gr < NT) {
                __half* dst = act + ((long long)(b * NT + gr)) * ACTW + h * 64;
#pragma unroll
                for (int nt = 0; nt < 8; nt++)
                    *(__half2*)(dst + nt * 8 + 2 * tig) = __floats2half2_rn(oqa[nt][0], oqa[nt][1]);
            }
            if (gr + 8 < NT) {
                __half* dst = act + ((long long)(b * NT + gr + 8)) * ACTW + h * 64;
#pragma unroll
                for (int nt = 0; nt < 8; nt++)
                    *(__half2*)(dst + nt * 8 + 2 * tig) = __floats2half2_rn(oqa[nt][2], oqa[nt][3]);
            }
        }
        __syncthreads();

        // ok += P^T @ q
#pragma unroll
        for (int rc = 0; rc < 8; rc++) {
            uint32_t bq[4][4];
#pragma unroll
            for (int yb = 0; yb < 4; yb++)
                ldsm4t(bq[yb], sQ32 + (row0 + rc * 16 + lm16) * 144 + lmHi + yb * 32);
#pragma unroll
            for (int mt = 0; mt < 2; mt++) {
                if (mt == 0 || w < 6) {
                    int t = w + mt * 8;
                    uint32_t tmp[4];
                    ldsm4t(tmp, sP32 + (rc * 16 + lm16) * 464 + lmHi + t * 32);
                    uint32_t ap[4] = { tmp[0], tmp[2], tmp[1], tmp[3] };
#pragma unroll
                    for (int nt = 0; nt < 8; nt++)
                        MMA16(okacc[mt][nt], ap,
                              bq[nt >> 1][(nt & 1) * 2], bq[nt >> 1][(nt & 1) * 2 + 1]);
                }
            }
        }
        __syncthreads();
    }

#pragma unroll
    for (int mt = 0; mt < 2; mt++) {
        if (mt == 0 || w < 6) {
            int t = w + mt * 8;
            int c0 = t * 16 + grp;
            if (c0 < NT) {
                __half* dst = act + ((long long)(b * NT + c0)) * ACTW + 768 + h * 64;
#pragma unroll
                for (int nt = 0; nt < 8; nt++)
                    *(__half2*)(dst + nt * 8 + 2 * tig) = __floats2half2_rn(okacc[mt][nt][0], okacc[mt][nt][1]);
            }
            if (c0 + 8 < NT) {
                __half* dst = act + ((long long)(b * NT + c0 + 8)) * ACTW + 768 + h * 64;
#pragma unroll
                for (int nt = 0; nt < 8; nt++)
                    *(__half2*)(dst + nt * 8 + 2 * tig) = __floats2half2_rn(okacc[mt][nt][2], okacc[mt][nt][3]);
            }
        }
    }
}

// ================= layernorm (fp32 in, half out) =================
__device__ __forceinline__ float block_sum256(float v, float* red) {
    int lane = threadIdx.x & 31, w = threadIdx.x >> 5;
#pragma unroll
    for (int o = 16; o > 0; o >>= 1) v += __shfl_xor_sync(0xffffffffu, v, o);
    if (lane == 0) red[w] = v;
    __syncthreads();
    float s = 0.f;
#pragma unroll
    for (int i = 0; i < 8; i++) s += red[i];
    __syncthreads();
    return s;
}

__global__ void lnorm_kernel(const float* __restrict__ x, __half* __restrict__ g,
                             const float* __restrict__ gamma_p,
                             const float* __restrict__ delta, int skipcls)
{
    __shared__ float red[8];
    int r = blockIdx.x;
    const float* xr;
    __half* gr;
    if (skipcls) {
        int b = r / NP, i = r - b * NP;
        xr = x + (long long)(b * NT + 1 + i) * D_;
        gr = g + (long long)r * D_;
    } else {
        xr = x + (long long)r * D_;
        gr = g + (long long)r * D_;
    }
    int t = threadIdx.x; // 256
    float v0 = xr[t], v1 = xr[t + 256], v2 = xr[t + 512];
    float mean = block_sum256(v0 + v1 + v2, red) * (1.f / 768.f);
    float c0 = v0 - mean, c1 = v1 - mean, c2 = v2 - mean;
    float var = block_sum256(c0*c0 + c1*c1 + c2*c2, red) * (1.f / 768.f);
    float rinv = rsqrtf(var + EPS_);
    float gm = gamma_p[0];
    gr[t]       = __float2half(gm * c0 * rinv + delta[t]);
    gr[t + 256] = __float2half(gm * c1 * rinv + delta[t + 256]);
    gr[t + 512] = __float2half(gm * c2 * rinv + delta[t + 512]);
}

// ================= weight prep =================
__global__ void build_wqk_kernel(const float* __restrict__ Wq, const float* __restrict__ Wk,
                                 __half* __restrict__ Wfwd, __half* __restrict__ Wback)
{
    int idx = blockIdx.x * 256 + threadIdx.x;
    if (idx >= 2 * D_ * D_) return;
    int which = idx >= D_ * D_;
    int r = idx - which * D_ * D_;
    int h = r / (D_ * Y_);
    int rem = r - h * (D_ * Y_);
    int d = rem / Y_;
    int y = rem - d * Y_;
    __half v = __float2half(which ? Wk[r] : Wq[r]);
    int hy = h * Y_ + y + which * D_;
    Wfwd[(long long)hy * D_ + d] = v;
    Wback[(long long)d * ACTW + hy] = v;
}

__global__ void build_xi_kernel(const float* __restrict__ Xi,
                                __half* __restrict__ Wfwd, __half* __restrict__ Wback)
{
    __shared__ __half t[32][33];
    int d0 = blockIdx.y * 32, m0 = blockIdx.x * 32;
    int tx = threadIdx.x & 31, ty = threadIdx.x >> 5;
#pragma unroll
    for (int i = 0; i < 32; i += 8) {
        __half v = __float2half(Xi[(long long)(d0 + ty + i) * M_ + m0 + tx]);
        Wback[(long long)(d0 + ty + i) * ACTW + 1536 + m0 + tx] = v;
        t[ty + i][tx] = v;
    }
    __syncthreads();
#pragma unroll
    for (int i = 0; i < 32; i += 8)
        Wfwd[(long long)(1536 + m0 + ty + i) * D_ + d0 + tx] = t[tx][ty + i];
}

__global__ void build_wt_kernel(const float* __restrict__ W, __half* __restrict__ WT)
{
    __shared__ __half t[32][33];
    int i0 = blockIdx.y * 32, j0 = blockIdx.x * 32;
    int tx = threadIdx.x & 31, ty = threadIdx.x >> 5;
#pragma unroll
    for (int i = 0; i < 32; i += 8)
        t[ty + i][tx] = __float2half(W[(long long)(i0 + ty + i) * D_ + j0 + tx]);
    __syncthreads();
#pragma unroll
    for (int i = 0; i < 32; i += 8)
        WT[(long long)(j0 + ty + i) * D_ + i0 + tx] = t[tx][ty + i];
}

// ================= misc =================
__global__ void patchify_kernel(const float* __restrict__ img, __half* __restrict__ out)
{
    int idx = blockIdx.x * 256 + threadIdx.x;
    if (idx >= B_ * NP * D_) return;
    int e = idx % D_;
    int rest = idx / D_;
    int p = rest % NP;
    int b = rest / NP;
    int c = e >> 8;
    int r = (e >> 4) & 15;
    int col = e & 15;
    int kh = p / 14, kw = p - kh * 14;
    out[idx] = __float2half(img[((long long)(b * 3 + c) * 224 + kh * 16 + r) * 224 + kw * 16 + col]);
}

__global__ void unpatchify_kernel(const float* __restrict__ dec, float* __restrict__ out)
{
    int idx = blockIdx.x * 256 + threadIdx.x;
    if (idx >= B_ * 3 * 224 * 224) return;
    int w = idx % 224;
    int rest = idx / 224;
    int h = rest % 224;
    rest /= 224;
    int c = rest % 3;
    int b = rest / 3;
    int kh = h >> 4, r = h & 15, kw = w >> 4, col = w & 15;
    out[idx] = dec[(long long)(b * NP + kh * 14 + kw) * D_ + c * 256 + r * 16 + col];
}

__global__ void build_x_kernel(const float* __restrict__ tok, const int* __restrict__ mask,
                               const float* __restrict__ cls, const float* __restrict__ mtok,
                               const float* __restrict__ pos, float* __restrict__ x)
{
    __shared__ int sm[NP];
    __shared__ unsigned char flag[NP];
    __shared__ int count_s;
    int b = blockIdx.x;
    int t = threadIdx.x; // 256
    if (t < NP) sm[t] = mask[b * NP + t];
    __syncthreads();
    if (t < NP) {
        int pref = 0;
        for (int j = 0; j < t; j++) pref += (sm[j] == 1);
        flag[t] = (sm[t] == 1 && pref < NMASK_) ? 1 : 0;
        if (t == NP - 1) count_s = pref + (sm[t] == 1);
    }
    __syncthreads();
    if (t == 0 && count_s < NMASK_) flag[0] = 1; // fill_value=0 padding hits token 0
    __syncthreads();
    for (int tk = 0; tk < NT; tk++) {
        const float* src;
        if (tk == 0) src = cls;
        else if (flag[tk - 1]) src = mtok;
        else src = tok + (long long)(b * NP + tk - 1) * D_;
        float* dst = x + (long long)(b * NT + tk) * D_;
        const float* pr = pos + (long long)tk * D_;
        for (int d = t; d < D_; d += 256) dst[d] = src[d] + pr[d];
    }
}

// ================= host wrappers =================
template<int EPI, int WM, int MINB, bool GUARD>
static void launch_bt(const __half* A, const __half* B, void* C, void* C2,
                      const float* bias, int Mtiles, int Ntiles, int K,
                      int lda, int ldb, int ldc, int Mv, int Nv, float alpha)
{
    int smem = 4 * (WM * 32 + 128) * 40 * 2;
    cudaFuncSetAttribute(hbt_kernel<EPI, WM, MINB, GUARD>,
                         cudaFuncAttributeMaxDynamicSharedMemorySize, smem);
    dim3 g(Ntiles, Mtiles, 1);
    hbt_kernel<EPI, WM, MINB, GUARD><<<g, 128, smem>>>(A, B, C, C2, bias, K,
                                                       lda, ldb, ldc, Mv, Nv, alpha);
}

extern "C" void kernel_launch(void* const* d_in, const int* in_sizes, int n_in,
                              void* d_out, int out_size)
{
    const float* img   = (const float*)d_in[0];
    const int*   mask  = (const int*)  d_in[1];
    const float* enc_W = (const float*)d_in[2];
    const float* enc_b = (const float*)d_in[3];
    const float* dec_W = (const float*)d_in[4];
    const float* dec_b = (const float*)d_in[5];
    const float* cls   = (const float*)d_in[6];
    const float* mtok  = (const float*)d_in[7];
    const float* pos   = (const float*)d_in[8];
    const float* Wq    = (const float*)d_in[9];
    const float* Wk    = (const float*)d_in[10];
    const float* Xi    = (const float*)d_in[11];
    const float* gamma = (const float*)d_in[12];
    const float* delta = (const float*)d_in[13];
    float* out = (float*)d_out;

    __half *ppatH, *pgH, *pqkH, *pact, *pWfwd, *pWback, *pencTh, *pdecTh;
    float *ptok, *px, *pdec;
    cudaGetSymbolAddress((void**)&ppatH, d_patches);
    cudaGetSymbolAddress((void**)&ptok,  d_tok);
    cudaGetSymbolAddress((void**)&px,    d_x);
    cudaGetSymbolAddress((void**)&pgH,   d_g);
    cudaGetSymbolAddress((void**)&pqkH,  d_qk);
    cudaGetSymbolAddress((void**)&pact,  d_act);
    cudaGetSymbolAddress((void**)&pWfwd, d_Wfwd);
    cudaGetSymbolAddress((void**)&pWback, d_Wback);
    cudaGetSymbolAddress((void**)&pencTh, d_encTh);
    cudaGetSymbolAddress((void**)&pdecTh, d_decTh);
    cudaGetSymbolAddress((void**)&pdec,  d_dec);

    const int ROWS  = B_ * NT;   // 3152
    const int ROWSE = B_ * NP;   // 3136

    // weight prep
    build_wqk_kernel<<<(2 * D_ * D_ + 255) / 256, 256>>>(Wq, Wk, pWfwd, pWback);
    build_xi_kernel<<<dim3(M_ / 32, D_ / 32), 256>>>(Xi, pWfwd, pWback);
    build_wt_kernel<<<dim3(24, 24), 256>>>(enc_W, pencTh);
    build_wt_kernel<<<dim3(24, 24), 256>>>(dec_W, pdecTh);

    // encode
    patchify_kernel<<<(B_ * NP * D_ + 255) / 256, 256>>>(img, ppatH);
    launch_bt<EPI_BIAS, 4, 2, true>(ppatH, pencTh, ptok, 0, enc_b,
        25, 6, D_, D_, D_, D_, ROWSE, D_, 0.f);
    build_x_kernel<<<B_, 256>>>(ptok, mask, cls, mtok, pos, px);

    int attn_smem = (2 * 256 * 72 + 128 * 232) * 2;   // 133120
    cudaFuncSetAttribute(attn_kernel,
                         cudaFuncAttributeMaxDynamicSharedMemorySize, attn_smem);

    for (int s = 0; s < NSTEPS_; s++) {
        lnorm_kernel<<<ROWS, 256>>>(px, pgH, gamma, delta, 0);
        // fused fwd: [q|k | Z] = g @ [WT ; XiT]
        launch_bt<EPI_QKZ, 4, 2, false>(pgH, pWfwd, pqkH, pact, 0,
            25, 36, D_, D_, D_, 0, 0, 0, 0.f);
        // fused attention: act[.,0..1535] <- [P@k | P^T@q]
        attn_kernel<<<B_ * HEADS_, 256, attn_smem>>>(pqkH, pact);
        // fused bwd: x += alpha * [oq|ok|Z] @ [W2 ; XiR]
        launch_bt<EPI_AXPY, 2, 3, false>(pact, pWback, px, 0, 0,
            50, 6, ACTW, ACTW, ACTW, D_, 0, 0, ALPHA_);
    }

    // decode
    lnorm_kernel<<<ROWSE, 256>>>(px, pgH, gamma, delta, 1);
    launch_bt<EPI_BIAS, 4, 2, true>(pgH, pdecTh, pdec, 0, dec_b,
        25, 6, D_, D_, D_, D_, ROWSE, D_, 0.f);
    unpatchify_kernel<<<(B_ * 3 * 224 * 224 + 255) / 256, 256>>>(pdec, out);
}